// round 13
// baseline (speedup 1.0000x reference)
#include <cuda_runtime.h>
#include <math.h>

#define B_ 1024
#define N_ 50000
#define D_ 256
#define NV4 (N_ / 4)        // 12500 float4 per row
#define WPR 25              // warps per row: 24 full segs of 512 + 1 seg of 212
#define SEG 512             // float4 per full warp segment
#define P1_TPB 256
#define DT_BLOCKS 128       // dterm blocks: bids [0, 128)
#define BCE_BLOCKS (B_ * WPR / 8)            // 3200 BCE blocks: bids [128, 3328)
#define FIN_BID (DT_BLOCKS + BCE_BLOCKS)     // finalizer block: bid 3328
#define P1_GRID (FIN_BID + 1)                // 3329
#define NBANK 8
// completion target: one per BCE warp + one per dterm block
#define DONE_TARGET (BCE_BLOCKS * (P1_TPB / 32) + DT_BLOCKS)   // 25728

// Per-row partials padded to 8 doubles (64B) for vector loads/stores:
// 0..2 sumexp(merged,text,rec), 3..5 dot, 6 sum(x), 7 pad
__device__ double g_row[B_][8];
// Banked dterm accumulators (max 16 serialized RMWs per address)
__device__ double g_bank[NBANK][3];
__device__ unsigned int g_cnt;

__device__ __forceinline__ float sum_exp4(float4 v) {
    return __expf(v.x) + __expf(v.y) + __expf(v.z) + __expf(v.w);
}
__device__ __forceinline__ float dot4(float4 a, float4 b) {
    return a.x * b.x + a.y * b.y + a.z * b.z + a.w * b.w;
}

// Single fused kernel:
//   bids [0,128)      : [B,D] dterms (overlap with the big stream)
//   bids [128, 3328)  : proven warp-centric BCE streaming (hot path untouched)
//   bid  3328         : spin-wait finalizer (1 CTA slot; polls g_cnt)
__global__ __launch_bounds__(P1_TPB, 4)
void pass1_kernel(const float4* __restrict__ recon,
                  const float4* __restrict__ xmat,
                  const float4* __restrict__ text,
                  const float4* __restrict__ rec,
                  const float4* __restrict__ z,
                  const float4* __restrict__ mu,
                  const float4* __restrict__ lv,
                  const float4* __restrict__ pmu,
                  const float4* __restrict__ plv,
                  float* __restrict__ out)
{
    const int lane = threadIdx.x & 31;
    const int t    = threadIdx.x;
    const int w    = t >> 5;

    if (blockIdx.x == FIN_BID) {
        // ---------------- finalizer: wait for everyone ----------------
        if (t == 0) {
            while (atomicAdd(&g_cnt, 0u) != DONE_TARGET) __nanosleep(128);
        }
        __syncthreads();
        __threadfence();   // acquire: order the observation before g_row reads

        // 4 rows per thread: corrections in float (|c|~2.8e5; budget ~2.9e5
        // absolute on the 1024-row sum -> float rel ~1e-7 is 4 orders inside).
        float fc0 = 0.f, fc1 = 0.f, fc2 = 0.f;
        #pragma unroll
        for (int r = 0; r < 4; r++) {
            const int row = t + r * P1_TPB;
            const double2* rp = reinterpret_cast<const double2*>(&g_row[row][0]);
            double2 v0 = rp[0];   // se0, se1
            double2 v1 = rp[1];   // se2, dd0
            double2 v2 = rp[2];   // dd1, dd2
            double2 v3 = rp[3];   // sx, pad

            float sxf = (float)v3.x;
            fc0 += (float)v1.y - logf((float)v0.x) * sxf;
            fc1 += (float)v2.x - logf((float)v0.y) * sxf;
            fc2 += (float)v2.y - logf((float)v1.x) * sxf;

            // reset this row for next graph replay
            double2* wp = reinterpret_cast<double2*>(&g_row[row][0]);
            double2 zz2; zz2.x = 0.0; zz2.y = 0.0;
            wp[0] = zz2; wp[1] = zz2; wp[2] = zz2; wp[3] = zz2;
        }

        // reduce in double from here on
        double c0 = (double)fc0, c1 = (double)fc1, c2 = (double)fc2;
        #pragma unroll
        for (int o = 16; o > 0; o >>= 1) {
            c0 += __shfl_down_sync(0xffffffffu, c0, o);
            c1 += __shfl_down_sync(0xffffffffu, c1, o);
            c2 += __shfl_down_sync(0xffffffffu, c2, o);
        }
        __shared__ double sh[3][8];
        if (lane == 0) { sh[0][w] = c0; sh[1][w] = c1; sh[2][w] = c2; }
        __syncthreads();

        if (w == 0) {
            // dterm banks
            double s0 = 0.0, s1 = 0.0, s2 = 0.0;
            if (lane < NBANK) {
                s0 = g_bank[lane][0];
                s1 = g_bank[lane][1];
                s2 = g_bank[lane][2];
                g_bank[lane][0] = 0.0;   // reset for next replay
                g_bank[lane][1] = 0.0;
                g_bank[lane][2] = 0.0;
            }
            #pragma unroll
            for (int o = 16; o > 0; o >>= 1) {
                s0 += __shfl_down_sync(0xffffffffu, s0, o);
                s1 += __shfl_down_sync(0xffffffffu, s1, o);
                s2 += __shfl_down_sync(0xffffffffu, s2, o);
            }

            if (lane == 0) {
                double a0 = 0.0, a1 = 0.0, a2 = 0.0;
                #pragma unroll
                for (int q = 0; q < 8; q++) {
                    a0 += sh[0][q]; a1 += sh[1][q]; a2 += sh[2][q];
                }

                const double invBN = 1.0 / ((double)B_ * (double)N_);
                const double invBD = 1.0 / ((double)B_ * (double)D_);

                double bce_merged = -a0 * invBN;
                double bce_text   = -a1 * invBN;
                double bce_rec    = -a2 * invBN;
                double BCE = (bce_merged + bce_text + bce_rec) / 3.0;

                double KLD1 = -0.5 * s0 * invBD;
                double KLD2 = s1 * invBD;            // ANNEAL = 1
                double wass = s2 / (double)B_;

                double lval = BCE + 0.5 * (KLD1 + KLD2) + wass;  // ANNEAL/2, EPS=1

                out[0] = (float)lval;
                out[1] = (float)BCE;
                out[2] = (float)wass;
                out[3] = (float)bce_rec;
                out[4] = (float)bce_text;
                out[5] = (float)bce_merged;

                g_cnt = 0u;   // reset for next graph replay
            }
        }
        return;
    }

    if (blockIdx.x < DT_BLOCKS) {
        // ---- [B,D] elementwise terms: 2 float4 per thread ----
        const int gtid = blockIdx.x * P1_TPB + t;
        const int NT   = DT_BLOCKS * P1_TPB;   // 32768; n4 = 65536

        float k1 = 0.f, k2 = 0.f, wv = 0.f;
        #pragma unroll
        for (int rep = 0; rep < 2; rep++) {
            const int i = gtid + rep * NT;
            float4 m4  = mu[i];
            float4 l4  = lv[i];
            float4 pm4 = pmu[i];
            float4 pl4 = plv[i];
            float4 z4  = z[i];

            #pragma unroll
            for (int q = 0; q < 4; q++) {
                float m  = (&m4.x)[q];
                float l  = (&l4.x)[q];
                float pm = (&pm4.x)[q];
                float pl = (&pl4.x)[q];
                float zz = (&z4.x)[q];

                float el  = __expf(l);
                float epl = __expf(pl);

                k1 += 1.f + l - m * m - el;
                float dz = zz - pm;
                k2 += -0.5f * pl - 0.5f * dz * dz * __expf(-pl) + 0.5f * zz * zz;
                float dm = m - pm;
                wv += dm * dm + el + epl - 2.f * sqrtf(el * epl);
            }
        }

        __shared__ float shf[3][8];
        float vals[3] = {k1, k2, wv};
        #pragma unroll
        for (int j = 0; j < 3; j++) {
            float v = vals[j];
            #pragma unroll
            for (int o = 16; o > 0; o >>= 1) v += __shfl_down_sync(0xffffffffu, v, o);
            if (lane == 0) shf[j][w] = v;
        }
        __syncthreads();

        if (t == 0) {
            float s0 = 0.f, s1 = 0.f, s2 = 0.f;
            #pragma unroll
            for (int q = 0; q < 8; q++) { s0 += shf[0][q]; s1 += shf[1][q]; s2 += shf[2][q]; }
            const int bk = blockIdx.x & (NBANK - 1);
            atomicAdd(&g_bank[bk][0], (double)s0);
            atomicAdd(&g_bank[bk][1], (double)s1);
            atomicAdd(&g_bank[bk][2], (double)s2);
            __threadfence();
            atomicAdd(&g_cnt, 1u);
        }
        return;
    }

    // ---- BCE streaming (hot path, byte-identical logic) ----
    const int gw   = ((blockIdx.x - DT_BLOCKS) * P1_TPB + t) >> 5;
    const int row  = gw / WPR;
    const int seg  = gw - row * WPR;

    const size_t base = (size_t)row * NV4;
    const float4* __restrict__ R = recon + base;
    const float4* __restrict__ X = xmat  + base;
    const float4* __restrict__ T = text  + base;
    const float4* __restrict__ C = rec   + base;

    float se0 = 0.f, se1 = 0.f, se2 = 0.f;
    float d0 = 0.f, d1 = 0.f, d2 = 0.f;
    float sx = 0.f;

    if (seg < 24) {
        // full 512-float4 segment: 8 unrolled pairs, 8 LDG.128 in flight
        int i = seg * SEG + lane;
        #pragma unroll 1
        for (int p = 0; p < 8; p++, i += 64) {
            float4 r0 = __ldcs(&R[i]);
            float4 x0 = __ldcs(&X[i]);
            float4 t0 = __ldcs(&T[i]);
            float4 c0 = __ldcs(&C[i]);
            float4 r1 = __ldcs(&R[i + 32]);
            float4 x1 = __ldcs(&X[i + 32]);
            float4 t1 = __ldcs(&T[i + 32]);
            float4 c1 = __ldcs(&C[i + 32]);

            se0 += sum_exp4(r0) + sum_exp4(r1);
            se1 += sum_exp4(t0) + sum_exp4(t1);
            se2 += sum_exp4(c0) + sum_exp4(c1);
            d0  += dot4(r0, x0) + dot4(r1, x1);
            d1  += dot4(t0, x0) + dot4(t1, x1);
            d2  += dot4(c0, x0) + dot4(c1, x1);
            sx  += x0.x + x0.y + x0.z + x0.w + x1.x + x1.y + x1.z + x1.w;
        }
    } else {
        // tail segment: columns [12288, 12500) = 212 float4
        for (int i = 24 * SEG + lane; i < NV4; i += 32) {
            float4 r0 = __ldcs(&R[i]);
            float4 x0 = __ldcs(&X[i]);
            float4 t0 = __ldcs(&T[i]);
            float4 c0 = __ldcs(&C[i]);
            se0 += sum_exp4(r0);
            se1 += sum_exp4(t0);
            se2 += sum_exp4(c0);
            d0  += dot4(r0, x0);
            d1  += dot4(t0, x0);
            d2  += dot4(c0, x0);
            sx  += x0.x + x0.y + x0.z + x0.w;
        }
    }

    // Warp reduce 7 scalars, one double atomicAdd each per warp (spread addrs).
    float vals[7] = {se0, se1, se2, d0, d1, d2, sx};
    #pragma unroll
    for (int j = 0; j < 7; j++) {
        float v = vals[j];
        #pragma unroll
        for (int o = 16; o > 0; o >>= 1) v += __shfl_down_sync(0xffffffffu, v, o);
        vals[j] = v;
    }
    if (lane == 0) {
        #pragma unroll
        for (int j = 0; j < 7; j++) atomicAdd(&g_row[row][j], (double)vals[j]);
        __threadfence();            // release: row atomics visible before count
        atomicAdd(&g_cnt, 1u);
    }
}

extern "C" void kernel_launch(void* const* d_in, const int* in_sizes, int n_in,
                              void* d_out, int out_size) {
    const float* recon = (const float*)d_in[0];
    const float* x     = (const float*)d_in[1];
    const float* z     = (const float*)d_in[2];
    const float* mu    = (const float*)d_in[3];
    const float* lv    = (const float*)d_in[4];
    const float* text  = (const float*)d_in[5];
    const float* rec   = (const float*)d_in[6];
    const float* pmu   = (const float*)d_in[7];
    const float* plv   = (const float*)d_in[8];
    // d_in[9] = train_items, unused by the loss

    pass1_kernel<<<P1_GRID, P1_TPB>>>((const float4*)recon, (const float4*)x,
                                      (const float4*)text, (const float4*)rec,
                                      (const float4*)z, (const float4*)mu,
                                      (const float4*)lv, (const float4*)pmu,
                                      (const float4*)plv, (float*)d_out);
}

// round 14
// speedup vs baseline: 1.0993x; 1.0993x over previous
#include <cuda_runtime.h>
#include <math.h>

#define B_ 1024
#define N_ 50000
#define D_ 256
#define NV4 (N_ / 4)        // 12500 float4 per row
#define WPR 25              // warps per row: 24 full segs of 512 + 1 seg of 212
#define SEG 512             // float4 per full warp segment
#define P1_TPB 256
#define DT_BLOCKS 128       // dterm blocks prepended: bids [0, 128)
#define BCE_BLOCKS (B_ * WPR / 8)          // 3200 BCE blocks: bids [128, 3328)
#define P1_GRID (DT_BLOCKS + BCE_BLOCKS)   // 3328
#define NBANK 8

// Per-row partials padded to 8 doubles (64B) for vector loads/stores:
// 0..2 sumexp(merged,text,rec), 3..5 dot, 6 sum(x), 7 pad
__device__ double g_row[B_][8];
// Banked dterm accumulators (max 16 serialized RMWs per address)
__device__ double g_bank[NBANK][3];

__device__ __forceinline__ float sum_exp4(float4 v) {
    return __expf(v.x) + __expf(v.y) + __expf(v.z) + __expf(v.w);
}
__device__ __forceinline__ float dot4(float4 a, float4 b) {
    return a.x * b.x + a.y * b.y + a.z * b.z + a.w * b.w;
}

// Pass 1 (byte-identical to the round-12 best): bids [0,128) = [B,D] dterms
// (overlapped with the big stream); bids [128, 3328) = the proven
// warp-centric BCE streaming path, untouched.
__global__ __launch_bounds__(P1_TPB, 4)
void pass1_kernel(const float4* __restrict__ recon,
                  const float4* __restrict__ xmat,
                  const float4* __restrict__ text,
                  const float4* __restrict__ rec,
                  const float4* __restrict__ z,
                  const float4* __restrict__ mu,
                  const float4* __restrict__ lv,
                  const float4* __restrict__ pmu,
                  const float4* __restrict__ plv)
{
    const int lane = threadIdx.x & 31;

    if (blockIdx.x < DT_BLOCKS) {
        // ---- [B,D] elementwise terms: 2 float4 per thread ----
        const int t    = threadIdx.x;
        const int w    = t >> 5;
        const int gtid = blockIdx.x * P1_TPB + t;
        const int NT   = DT_BLOCKS * P1_TPB;   // 32768; n4 = 65536

        float k1 = 0.f, k2 = 0.f, wv = 0.f;
        #pragma unroll
        for (int rep = 0; rep < 2; rep++) {
            const int i = gtid + rep * NT;
            float4 m4  = mu[i];
            float4 l4  = lv[i];
            float4 pm4 = pmu[i];
            float4 pl4 = plv[i];
            float4 z4  = z[i];

            #pragma unroll
            for (int q = 0; q < 4; q++) {
                float m  = (&m4.x)[q];
                float l  = (&l4.x)[q];
                float pm = (&pm4.x)[q];
                float pl = (&pl4.x)[q];
                float zz = (&z4.x)[q];

                float el  = __expf(l);
                float epl = __expf(pl);

                k1 += 1.f + l - m * m - el;
                float dz = zz - pm;
                k2 += -0.5f * pl - 0.5f * dz * dz * __expf(-pl) + 0.5f * zz * zz;
                float dm = m - pm;
                wv += dm * dm + el + epl - 2.f * sqrtf(el * epl);
            }
        }

        __shared__ float sh[3][8];
        float vals[3] = {k1, k2, wv};
        #pragma unroll
        for (int j = 0; j < 3; j++) {
            float v = vals[j];
            #pragma unroll
            for (int o = 16; o > 0; o >>= 1) v += __shfl_down_sync(0xffffffffu, v, o);
            if (lane == 0) sh[j][w] = v;
        }
        __syncthreads();

        if (t == 0) {
            float s0 = 0.f, s1 = 0.f, s2 = 0.f;
            #pragma unroll
            for (int q = 0; q < 8; q++) { s0 += sh[0][q]; s1 += sh[1][q]; s2 += sh[2][q]; }
            const int bk = blockIdx.x & (NBANK - 1);
            atomicAdd(&g_bank[bk][0], (double)s0);
            atomicAdd(&g_bank[bk][1], (double)s1);
            atomicAdd(&g_bank[bk][2], (double)s2);
        }
        return;
    }

    // ---- BCE streaming (hot path, byte-identical logic) ----
    const int gw   = ((blockIdx.x - DT_BLOCKS) * P1_TPB + threadIdx.x) >> 5;
    const int row  = gw / WPR;
    const int seg  = gw - row * WPR;

    const size_t base = (size_t)row * NV4;
    const float4* __restrict__ R = recon + base;
    const float4* __restrict__ X = xmat  + base;
    const float4* __restrict__ T = text  + base;
    const float4* __restrict__ C = rec   + base;

    float se0 = 0.f, se1 = 0.f, se2 = 0.f;
    float d0 = 0.f, d1 = 0.f, d2 = 0.f;
    float sx = 0.f;

    if (seg < 24) {
        // full 512-float4 segment: 8 unrolled pairs, 8 LDG.128 in flight
        int i = seg * SEG + lane;
        #pragma unroll 1
        for (int p = 0; p < 8; p++, i += 64) {
            float4 r0 = __ldcs(&R[i]);
            float4 x0 = __ldcs(&X[i]);
            float4 t0 = __ldcs(&T[i]);
            float4 c0 = __ldcs(&C[i]);
            float4 r1 = __ldcs(&R[i + 32]);
            float4 x1 = __ldcs(&X[i + 32]);
            float4 t1 = __ldcs(&T[i + 32]);
            float4 c1 = __ldcs(&C[i + 32]);

            se0 += sum_exp4(r0) + sum_exp4(r1);
            se1 += sum_exp4(t0) + sum_exp4(t1);
            se2 += sum_exp4(c0) + sum_exp4(c1);
            d0  += dot4(r0, x0) + dot4(r1, x1);
            d1  += dot4(t0, x0) + dot4(t1, x1);
            d2  += dot4(c0, x0) + dot4(c1, x1);
            sx  += x0.x + x0.y + x0.z + x0.w + x1.x + x1.y + x1.z + x1.w;
        }
    } else {
        // tail segment: columns [12288, 12500) = 212 float4
        for (int i = 24 * SEG + lane; i < NV4; i += 32) {
            float4 r0 = __ldcs(&R[i]);
            float4 x0 = __ldcs(&X[i]);
            float4 t0 = __ldcs(&T[i]);
            float4 c0 = __ldcs(&C[i]);
            se0 += sum_exp4(r0);
            se1 += sum_exp4(t0);
            se2 += sum_exp4(c0);
            d0  += dot4(r0, x0);
            d1  += dot4(t0, x0);
            d2  += dot4(c0, x0);
            sx  += x0.x + x0.y + x0.z + x0.w;
        }
    }

    // Warp reduce 7 scalars, one double atomicAdd each per warp (spread addrs).
    float vals[7] = {se0, se1, se2, d0, d1, d2, sx};
    #pragma unroll
    for (int j = 0; j < 7; j++) {
        float v = vals[j];
        #pragma unroll
        for (int o = 16; o > 0; o >>= 1) v += __shfl_down_sync(0xffffffffu, v, o);
        vals[j] = v;
    }
    if (lane == 0) {
        #pragma unroll
        for (int j = 0; j < 7; j++) atomicAdd(&g_row[row][j], (double)vals[j]);
    }
}

// Fixup: ONE block, 1024 threads, ALL-FLOAT math, zero protocol.
// Stream order guarantees pass1 completion; single block needs no fences,
// no atomics, no counter. 1 row per thread.
__global__ __launch_bounds__(1024)
void fixup_kernel(float* __restrict__ out)
{
    const int t    = threadIdx.x;   // == row
    const int lane = t & 31;
    const int w    = t >> 5;

    // vectorized row load: 4 x LDG.128
    const double2* rp = reinterpret_cast<const double2*>(&g_row[t][0]);
    double2 v0 = rp[0];   // se0, se1
    double2 v1 = rp[1];   // se2, dd0
    double2 v2 = rp[2];   // dd1, dd2
    double2 v3 = rp[3];   // sx, pad

    // float corrections: |c|~2.8e5, sum budget ~2.9e5 abs -> 3 orders margin.
    float sxf = (float)v3.x;
    float c0 = (float)v1.y - logf((float)v0.x) * sxf;
    float c1 = (float)v2.x - logf((float)v0.y) * sxf;
    float c2 = (float)v2.y - logf((float)v1.x) * sxf;

    // reset this row for next graph replay (4 x STG.128)
    double2* wp = reinterpret_cast<double2*>(&g_row[t][0]);
    double2 zz2; zz2.x = 0.0; zz2.y = 0.0;
    wp[0] = zz2; wp[1] = zz2; wp[2] = zz2; wp[3] = zz2;

    // warp reduce (float shuffles)
    #pragma unroll
    for (int o = 16; o > 0; o >>= 1) {
        c0 += __shfl_down_sync(0xffffffffu, c0, o);
        c1 += __shfl_down_sync(0xffffffffu, c1, o);
        c2 += __shfl_down_sync(0xffffffffu, c2, o);
    }

    __shared__ float sh[3][32];
    if (lane == 0) { sh[0][w] = c0; sh[1][w] = c1; sh[2][w] = c2; }
    __syncthreads();

    if (w != 0) return;

    // warp 0: fold 32 block partials + 8 dterm banks, finalize in float
    float a0 = sh[0][lane], a1 = sh[1][lane], a2 = sh[2][lane];

    float s0 = 0.f, s1 = 0.f, s2 = 0.f;
    if (lane < NBANK) {
        s0 = (float)g_bank[lane][0];
        s1 = (float)g_bank[lane][1];
        s2 = (float)g_bank[lane][2];
        g_bank[lane][0] = 0.0;   // reset for next replay
        g_bank[lane][1] = 0.0;
        g_bank[lane][2] = 0.0;
    }
    #pragma unroll
    for (int o = 16; o > 0; o >>= 1) {
        a0 += __shfl_down_sync(0xffffffffu, a0, o);
        a1 += __shfl_down_sync(0xffffffffu, a1, o);
        a2 += __shfl_down_sync(0xffffffffu, a2, o);
        s0 += __shfl_down_sync(0xffffffffu, s0, o);
        s1 += __shfl_down_sync(0xffffffffu, s1, o);
        s2 += __shfl_down_sync(0xffffffffu, s2, o);
    }

    if (lane == 0) {
        const float invBN = 1.0f / ((float)B_ * (float)N_);
        const float invBD = 1.0f / ((float)B_ * (float)D_);

        float bce_merged = -a0 * invBN;
        float bce_text   = -a1 * invBN;
        float bce_rec    = -a2 * invBN;
        float BCE = (bce_merged + bce_text + bce_rec) * (1.0f / 3.0f);

        float KLD1 = -0.5f * s0 * invBD;
        float KLD2 = s1 * invBD;            // ANNEAL = 1
        float wass = s2 * (1.0f / (float)B_);

        float lval = BCE + 0.5f * (KLD1 + KLD2) + wass;  // ANNEAL/2, EPSILON=1

        out[0] = lval;
        out[1] = BCE;
        out[2] = wass;
        out[3] = bce_rec;
        out[4] = bce_text;
        out[5] = bce_merged;
    }
}

extern "C" void kernel_launch(void* const* d_in, const int* in_sizes, int n_in,
                              void* d_out, int out_size) {
    const float* recon = (const float*)d_in[0];
    const float* x     = (const float*)d_in[1];
    const float* z     = (const float*)d_in[2];
    const float* mu    = (const float*)d_in[3];
    const float* lv    = (const float*)d_in[4];
    const float* text  = (const float*)d_in[5];
    const float* rec   = (const float*)d_in[6];
    const float* pmu   = (const float*)d_in[7];
    const float* plv   = (const float*)d_in[8];
    // d_in[9] = train_items, unused by the loss

    pass1_kernel<<<P1_GRID, P1_TPB>>>((const float4*)recon, (const float4*)x,
                                      (const float4*)text, (const float4*)rec,
                                      (const float4*)z, (const float4*)mu,
                                      (const float4*)lv, (const float4*)pmu,
                                      (const float4*)plv);
    fixup_kernel<<<1, 1024>>>((float*)d_out);
}

// round 15
// speedup vs baseline: 1.1091x; 1.0089x over previous
#include <cuda_runtime.h>
#include <math.h>

#define B_ 1024
#define N_ 50000
#define D_ 256
#define NV4 (N_ / 4)        // 12500 float4 per row
#define WPR 25              // warps per row: 24 full segs of 512 + 1 seg of 212
#define SEG 512             // float4 per full warp segment
#define P1_TPB 256
#define DT_BLOCKS 128       // dterm blocks prepended: bids [0, 128)
#define BCE_BLOCKS (B_ * WPR / 8)          // 3200 BCE blocks: bids [128, 3328)
#define P1_GRID (DT_BLOCKS + BCE_BLOCKS)   // 3328
#define NBANK 8

// Per-row partials in FLOAT, padded to 8 (32B) for vector loads/stores:
// 0..2 sumexp(merged,text,rec), 3..5 dot, 6 sum(x), 7 pad.
// Float atomic accumulation: 25 partials/row -> rel err ~1e-6, 3-4 orders
// inside the 1e-3 budget (audit in commit message).
__device__ float g_row[B_][8];
// Banked dterm accumulators (max 16 serialized RMWs per address)
__device__ double g_bank[NBANK][3];

__device__ __forceinline__ float sum_exp4(float4 v) {
    return __expf(v.x) + __expf(v.y) + __expf(v.z) + __expf(v.w);
}
__device__ __forceinline__ float dot4(float4 a, float4 b) {
    return a.x * b.x + a.y * b.y + a.z * b.z + a.w * b.w;
}

// Pass 1: bids [0,128) = [B,D] dterms (overlapped with the big stream);
// bids [128, 3328) = the proven warp-centric BCE streaming path. Hot loop
// byte-identical; epilogue atomics switched to float (RED.F32).
__global__ __launch_bounds__(P1_TPB, 4)
void pass1_kernel(const float4* __restrict__ recon,
                  const float4* __restrict__ xmat,
                  const float4* __restrict__ text,
                  const float4* __restrict__ rec,
                  const float4* __restrict__ z,
                  const float4* __restrict__ mu,
                  const float4* __restrict__ lv,
                  const float4* __restrict__ pmu,
                  const float4* __restrict__ plv)
{
    const int lane = threadIdx.x & 31;

    if (blockIdx.x < DT_BLOCKS) {
        // ---- [B,D] elementwise terms: 2 float4 per thread ----
        const int t    = threadIdx.x;
        const int w    = t >> 5;
        const int gtid = blockIdx.x * P1_TPB + t;
        const int NT   = DT_BLOCKS * P1_TPB;   // 32768; n4 = 65536

        float k1 = 0.f, k2 = 0.f, wv = 0.f;
        #pragma unroll
        for (int rep = 0; rep < 2; rep++) {
            const int i = gtid + rep * NT;
            float4 m4  = mu[i];
            float4 l4  = lv[i];
            float4 pm4 = pmu[i];
            float4 pl4 = plv[i];
            float4 z4  = z[i];

            #pragma unroll
            for (int q = 0; q < 4; q++) {
                float m  = (&m4.x)[q];
                float l  = (&l4.x)[q];
                float pm = (&pm4.x)[q];
                float pl = (&pl4.x)[q];
                float zz = (&z4.x)[q];

                float el  = __expf(l);
                float epl = __expf(pl);

                k1 += 1.f + l - m * m - el;
                float dz = zz - pm;
                k2 += -0.5f * pl - 0.5f * dz * dz * __expf(-pl) + 0.5f * zz * zz;
                float dm = m - pm;
                wv += dm * dm + el + epl - 2.f * sqrtf(el * epl);
            }
        }

        __shared__ float sh[3][8];
        float vals[3] = {k1, k2, wv};
        #pragma unroll
        for (int j = 0; j < 3; j++) {
            float v = vals[j];
            #pragma unroll
            for (int o = 16; o > 0; o >>= 1) v += __shfl_down_sync(0xffffffffu, v, o);
            if (lane == 0) sh[j][w] = v;
        }
        __syncthreads();

        if (t == 0) {
            float s0 = 0.f, s1 = 0.f, s2 = 0.f;
            #pragma unroll
            for (int q = 0; q < 8; q++) { s0 += sh[0][q]; s1 += sh[1][q]; s2 += sh[2][q]; }
            const int bk = blockIdx.x & (NBANK - 1);
            atomicAdd(&g_bank[bk][0], (double)s0);
            atomicAdd(&g_bank[bk][1], (double)s1);
            atomicAdd(&g_bank[bk][2], (double)s2);
        }
        return;
    }

    // ---- BCE streaming (hot path, byte-identical logic) ----
    const int gw   = ((blockIdx.x - DT_BLOCKS) * P1_TPB + threadIdx.x) >> 5;
    const int row  = gw / WPR;
    const int seg  = gw - row * WPR;

    const size_t base = (size_t)row * NV4;
    const float4* __restrict__ R = recon + base;
    const float4* __restrict__ X = xmat  + base;
    const float4* __restrict__ T = text  + base;
    const float4* __restrict__ C = rec   + base;

    float se0 = 0.f, se1 = 0.f, se2 = 0.f;
    float d0 = 0.f, d1 = 0.f, d2 = 0.f;
    float sx = 0.f;

    if (seg < 24) {
        // full 512-float4 segment: 8 unrolled pairs, 8 LDG.128 in flight
        int i = seg * SEG + lane;
        #pragma unroll 1
        for (int p = 0; p < 8; p++, i += 64) {
            float4 r0 = __ldcs(&R[i]);
            float4 x0 = __ldcs(&X[i]);
            float4 t0 = __ldcs(&T[i]);
            float4 c0 = __ldcs(&C[i]);
            float4 r1 = __ldcs(&R[i + 32]);
            float4 x1 = __ldcs(&X[i + 32]);
            float4 t1 = __ldcs(&T[i + 32]);
            float4 c1 = __ldcs(&C[i + 32]);

            se0 += sum_exp4(r0) + sum_exp4(r1);
            se1 += sum_exp4(t0) + sum_exp4(t1);
            se2 += sum_exp4(c0) + sum_exp4(c1);
            d0  += dot4(r0, x0) + dot4(r1, x1);
            d1  += dot4(t0, x0) + dot4(t1, x1);
            d2  += dot4(c0, x0) + dot4(c1, x1);
            sx  += x0.x + x0.y + x0.z + x0.w + x1.x + x1.y + x1.z + x1.w;
        }
    } else {
        // tail segment: columns [12288, 12500) = 212 float4
        for (int i = 24 * SEG + lane; i < NV4; i += 32) {
            float4 r0 = __ldcs(&R[i]);
            float4 x0 = __ldcs(&X[i]);
            float4 t0 = __ldcs(&T[i]);
            float4 c0 = __ldcs(&C[i]);
            se0 += sum_exp4(r0);
            se1 += sum_exp4(t0);
            se2 += sum_exp4(c0);
            d0  += dot4(r0, x0);
            d1  += dot4(t0, x0);
            d2  += dot4(c0, x0);
            sx  += x0.x + x0.y + x0.z + x0.w;
        }
    }

    // Warp reduce 7 scalars, one FLOAT atomicAdd each per warp (spread addrs).
    float vals[7] = {se0, se1, se2, d0, d1, d2, sx};
    #pragma unroll
    for (int j = 0; j < 7; j++) {
        float v = vals[j];
        #pragma unroll
        for (int o = 16; o > 0; o >>= 1) v += __shfl_down_sync(0xffffffffu, v, o);
        vals[j] = v;
    }
    if (lane == 0) {
        #pragma unroll
        for (int j = 0; j < 7; j++) atomicAdd(&g_row[row][j], vals[j]);
    }
}

// Fixup: ONE block, 1024 threads, all-float, zero protocol. 1 row/thread.
// Memory ops per thread: 2 LDG.128 + 2 STG.128 (was 4+4 with doubles).
__global__ __launch_bounds__(1024)
void fixup_kernel(float* __restrict__ out)
{
    const int t    = threadIdx.x;   // == row
    const int lane = t & 31;
    const int w    = t >> 5;

    // vectorized row load: 2 x LDG.128
    const float4* rp = reinterpret_cast<const float4*>(&g_row[t][0]);
    float4 u0 = rp[0];   // se0, se1, se2, dd0
    float4 u1 = rp[1];   // dd1, dd2, sx, pad

    // float corrections: |c|~2.8e5, sum budget ~2.9e5 abs -> wide margin.
    float sxf = u1.z;
    float c0 = u0.w - logf(u0.x) * sxf;
    float c1 = u1.x - logf(u0.y) * sxf;
    float c2 = u1.y - logf(u0.z) * sxf;

    // reset this row for next graph replay (2 x STG.128)
    float4* wp = reinterpret_cast<float4*>(&g_row[t][0]);
    float4 zz4; zz4.x = 0.f; zz4.y = 0.f; zz4.z = 0.f; zz4.w = 0.f;
    wp[0] = zz4; wp[1] = zz4;

    // warp reduce (float shuffles)
    #pragma unroll
    for (int o = 16; o > 0; o >>= 1) {
        c0 += __shfl_down_sync(0xffffffffu, c0, o);
        c1 += __shfl_down_sync(0xffffffffu, c1, o);
        c2 += __shfl_down_sync(0xffffffffu, c2, o);
    }

    __shared__ float sh[3][32];
    if (lane == 0) { sh[0][w] = c0; sh[1][w] = c1; sh[2][w] = c2; }
    __syncthreads();

    if (w != 0) return;

    // warp 0: fold 32 block partials + 8 dterm banks, finalize in float
    float a0 = sh[0][lane], a1 = sh[1][lane], a2 = sh[2][lane];

    float s0 = 0.f, s1 = 0.f, s2 = 0.f;
    if (lane < NBANK) {
        s0 = (float)g_bank[lane][0];
        s1 = (float)g_bank[lane][1];
        s2 = (float)g_bank[lane][2];
        g_bank[lane][0] = 0.0;   // reset for next replay
        g_bank[lane][1] = 0.0;
        g_bank[lane][2] = 0.0;
    }
    #pragma unroll
    for (int o = 16; o > 0; o >>= 1) {
        a0 += __shfl_down_sync(0xffffffffu, a0, o);
        a1 += __shfl_down_sync(0xffffffffu, a1, o);
        a2 += __shfl_down_sync(0xffffffffu, a2, o);
        s0 += __shfl_down_sync(0xffffffffu, s0, o);
        s1 += __shfl_down_sync(0xffffffffu, s1, o);
        s2 += __shfl_down_sync(0xffffffffu, s2, o);
    }

    if (lane == 0) {
        const float invBN = 1.0f / ((float)B_ * (float)N_);
        const float invBD = 1.0f / ((float)B_ * (float)D_);

        float bce_merged = -a0 * invBN;
        float bce_text   = -a1 * invBN;
        float bce_rec    = -a2 * invBN;
        float BCE = (bce_merged + bce_text + bce_rec) * (1.0f / 3.0f);

        float KLD1 = -0.5f * s0 * invBD;
        float KLD2 = s1 * invBD;            // ANNEAL = 1
        float wass = s2 * (1.0f / (float)B_);

        float lval = BCE + 0.5f * (KLD1 + KLD2) + wass;  // ANNEAL/2, EPSILON=1

        out[0] = lval;
        out[1] = BCE;
        out[2] = wass;
        out[3] = bce_rec;
        out[4] = bce_text;
        out[5] = bce_merged;
    }
}

extern "C" void kernel_launch(void* const* d_in, const int* in_sizes, int n_in,
                              void* d_out, int out_size) {
    const float* recon = (const float*)d_in[0];
    const float* x     = (const float*)d_in[1];
    const float* z     = (const float*)d_in[2];
    const float* mu    = (const float*)d_in[3];
    const float* lv    = (const float*)d_in[4];
    const float* text  = (const float*)d_in[5];
    const float* rec   = (const float*)d_in[6];
    const float* pmu   = (const float*)d_in[7];
    const float* plv   = (const float*)d_in[8];
    // d_in[9] = train_items, unused by the loss

    pass1_kernel<<<P1_GRID, P1_TPB>>>((const float4*)recon, (const float4*)x,
                                      (const float4*)text, (const float4*)rec,
                                      (const float4*)z, (const float4*)mu,
                                      (const float4*)lv, (const float4*)pmu,
                                      (const float4*)plv);
    fixup_kernel<<<1, 1024>>>((float*)d_out);
}

// round 16
// speedup vs baseline: 1.1182x; 1.0082x over previous
#include <cuda_runtime.h>
#include <math.h>

#define B_ 1024
#define N_ 50000
#define D_ 256
#define NV4 (N_ / 4)        // 12500 float4 per row
#define WPR 25              // warps per row: 24 full segs of 512 + 1 seg of 212
#define SEG 512             // float4 per full warp segment
#define P1_TPB 256
#define DT_BLOCKS 128       // dterm blocks prepended: bids [0, 128)
#define BCE_BLOCKS (B_ * WPR / 8)          // 3200 BCE blocks: bids [128, 3328)
#define P1_GRID (DT_BLOCKS + BCE_BLOCKS)   // 3328
#define NBANK 8

// Per-row partials in FLOAT, padded to 8 (32B) for vector loads/stores:
// 0..2 sumexp(merged,text,rec), 3..5 dot, 6 sum(x), 7 pad.
__device__ float g_row[B_][8];
// Banked dterm accumulators (max 16 serialized RMWs per address)
__device__ double g_bank[NBANK][3];

__device__ __forceinline__ float sum_exp4(float4 v) {
    return __expf(v.x) + __expf(v.y) + __expf(v.z) + __expf(v.w);
}
__device__ __forceinline__ float dot4(float4 a, float4 b) {
    return a.x * b.x + a.y * b.y + a.z * b.z + a.w * b.w;
}

// Pass 1 (byte-identical to the round-15 best): bids [0,128) = [B,D] dterms
// (overlapped with the big stream); bids [128, 3328) = the proven
// warp-centric BCE streaming path.
__global__ __launch_bounds__(P1_TPB, 4)
void pass1_kernel(const float4* __restrict__ recon,
                  const float4* __restrict__ xmat,
                  const float4* __restrict__ text,
                  const float4* __restrict__ rec,
                  const float4* __restrict__ z,
                  const float4* __restrict__ mu,
                  const float4* __restrict__ lv,
                  const float4* __restrict__ pmu,
                  const float4* __restrict__ plv)
{
    const int lane = threadIdx.x & 31;

    if (blockIdx.x < DT_BLOCKS) {
        // ---- [B,D] elementwise terms: 2 float4 per thread ----
        const int t    = threadIdx.x;
        const int w    = t >> 5;
        const int gtid = blockIdx.x * P1_TPB + t;
        const int NT   = DT_BLOCKS * P1_TPB;   // 32768; n4 = 65536

        float k1 = 0.f, k2 = 0.f, wv = 0.f;
        #pragma unroll
        for (int rep = 0; rep < 2; rep++) {
            const int i = gtid + rep * NT;
            float4 m4  = mu[i];
            float4 l4  = lv[i];
            float4 pm4 = pmu[i];
            float4 pl4 = plv[i];
            float4 z4  = z[i];

            #pragma unroll
            for (int q = 0; q < 4; q++) {
                float m  = (&m4.x)[q];
                float l  = (&l4.x)[q];
                float pm = (&pm4.x)[q];
                float pl = (&pl4.x)[q];
                float zz = (&z4.x)[q];

                float el  = __expf(l);
                float epl = __expf(pl);

                k1 += 1.f + l - m * m - el;
                float dz = zz - pm;
                k2 += -0.5f * pl - 0.5f * dz * dz * __expf(-pl) + 0.5f * zz * zz;
                float dm = m - pm;
                wv += dm * dm + el + epl - 2.f * sqrtf(el * epl);
            }
        }

        __shared__ float sh[3][8];
        float vals[3] = {k1, k2, wv};
        #pragma unroll
        for (int j = 0; j < 3; j++) {
            float v = vals[j];
            #pragma unroll
            for (int o = 16; o > 0; o >>= 1) v += __shfl_down_sync(0xffffffffu, v, o);
            if (lane == 0) sh[j][w] = v;
        }
        __syncthreads();

        if (t == 0) {
            float s0 = 0.f, s1 = 0.f, s2 = 0.f;
            #pragma unroll
            for (int q = 0; q < 8; q++) { s0 += sh[0][q]; s1 += sh[1][q]; s2 += sh[2][q]; }
            const int bk = blockIdx.x & (NBANK - 1);
            atomicAdd(&g_bank[bk][0], (double)s0);
            atomicAdd(&g_bank[bk][1], (double)s1);
            atomicAdd(&g_bank[bk][2], (double)s2);
        }
        return;
    }

    // ---- BCE streaming (hot path, byte-identical logic) ----
    const int gw   = ((blockIdx.x - DT_BLOCKS) * P1_TPB + threadIdx.x) >> 5;
    const int row  = gw / WPR;
    const int seg  = gw - row * WPR;

    const size_t base = (size_t)row * NV4;
    const float4* __restrict__ R = recon + base;
    const float4* __restrict__ X = xmat  + base;
    const float4* __restrict__ T = text  + base;
    const float4* __restrict__ C = rec   + base;

    float se0 = 0.f, se1 = 0.f, se2 = 0.f;
    float d0 = 0.f, d1 = 0.f, d2 = 0.f;
    float sx = 0.f;

    if (seg < 24) {
        // full 512-float4 segment: 8 unrolled pairs, 8 LDG.128 in flight
        int i = seg * SEG + lane;
        #pragma unroll 1
        for (int p = 0; p < 8; p++, i += 64) {
            float4 r0 = __ldcs(&R[i]);
            float4 x0 = __ldcs(&X[i]);
            float4 t0 = __ldcs(&T[i]);
            float4 c0 = __ldcs(&C[i]);
            float4 r1 = __ldcs(&R[i + 32]);
            float4 x1 = __ldcs(&X[i + 32]);
            float4 t1 = __ldcs(&T[i + 32]);
            float4 c1 = __ldcs(&C[i + 32]);

            se0 += sum_exp4(r0) + sum_exp4(r1);
            se1 += sum_exp4(t0) + sum_exp4(t1);
            se2 += sum_exp4(c0) + sum_exp4(c1);
            d0  += dot4(r0, x0) + dot4(r1, x1);
            d1  += dot4(t0, x0) + dot4(t1, x1);
            d2  += dot4(c0, x0) + dot4(c1, x1);
            sx  += x0.x + x0.y + x0.z + x0.w + x1.x + x1.y + x1.z + x1.w;
        }
    } else {
        // tail segment: columns [12288, 12500) = 212 float4
        for (int i = 24 * SEG + lane; i < NV4; i += 32) {
            float4 r0 = __ldcs(&R[i]);
            float4 x0 = __ldcs(&X[i]);
            float4 t0 = __ldcs(&T[i]);
            float4 c0 = __ldcs(&C[i]);
            se0 += sum_exp4(r0);
            se1 += sum_exp4(t0);
            se2 += sum_exp4(c0);
            d0  += dot4(r0, x0);
            d1  += dot4(t0, x0);
            d2  += dot4(c0, x0);
            sx  += x0.x + x0.y + x0.z + x0.w;
        }
    }

    // Warp reduce 7 scalars, one FLOAT atomicAdd each per warp (spread addrs).
    float vals[7] = {se0, se1, se2, d0, d1, d2, sx};
    #pragma unroll
    for (int j = 0; j < 7; j++) {
        float v = vals[j];
        #pragma unroll
        for (int o = 16; o > 0; o >>= 1) v += __shfl_down_sync(0xffffffffu, v, o);
        vals[j] = v;
    }
    if (lane == 0) {
        #pragma unroll
        for (int j = 0; j < 7; j++) atomicAdd(&g_row[row][j], vals[j]);
    }
}

// Fixup: ONE block, 1024 threads, all-float. Launched with PDL: scheduled
// while pass1 drains; cudaGridDependencySynchronize() releases it the moment
// pass1 completes (launch overhead hidden in pass1's tail wave).
__global__ __launch_bounds__(1024)
void fixup_kernel(float* __restrict__ out)
{
    cudaGridDependencySynchronize();   // wait for pass1 (PDL)

    const int t    = threadIdx.x;   // == row
    const int lane = t & 31;
    const int w    = t >> 5;

    // vectorized row load: 2 x LDG.128
    const float4* rp = reinterpret_cast<const float4*>(&g_row[t][0]);
    float4 u0 = rp[0];   // se0, se1, se2, dd0
    float4 u1 = rp[1];   // dd1, dd2, sx, pad

    // float corrections: |c|~2.8e5, sum budget ~2.9e5 abs -> wide margin.
    float sxf = u1.z;
    float c0 = u0.w - logf(u0.x) * sxf;
    float c1 = u1.x - logf(u0.y) * sxf;
    float c2 = u1.y - logf(u0.z) * sxf;

    // reset this row for next graph replay (2 x STG.128)
    float4* wp = reinterpret_cast<float4*>(&g_row[t][0]);
    float4 zz4; zz4.x = 0.f; zz4.y = 0.f; zz4.z = 0.f; zz4.w = 0.f;
    wp[0] = zz4; wp[1] = zz4;

    // warp reduce (float shuffles)
    #pragma unroll
    for (int o = 16; o > 0; o >>= 1) {
        c0 += __shfl_down_sync(0xffffffffu, c0, o);
        c1 += __shfl_down_sync(0xffffffffu, c1, o);
        c2 += __shfl_down_sync(0xffffffffu, c2, o);
    }

    __shared__ float sh[3][32];
    if (lane == 0) { sh[0][w] = c0; sh[1][w] = c1; sh[2][w] = c2; }
    __syncthreads();

    if (w != 0) return;

    // warp 0: fold 32 block partials + 8 dterm banks, finalize in float
    float a0 = sh[0][lane], a1 = sh[1][lane], a2 = sh[2][lane];

    float s0 = 0.f, s1 = 0.f, s2 = 0.f;
    if (lane < NBANK) {
        s0 = (float)g_bank[lane][0];
        s1 = (float)g_bank[lane][1];
        s2 = (float)g_bank[lane][2];
        g_bank[lane][0] = 0.0;   // reset for next replay
        g_bank[lane][1] = 0.0;
        g_bank[lane][2] = 0.0;
    }
    #pragma unroll
    for (int o = 16; o > 0; o >>= 1) {
        a0 += __shfl_down_sync(0xffffffffu, a0, o);
        a1 += __shfl_down_sync(0xffffffffu, a1, o);
        a2 += __shfl_down_sync(0xffffffffu, a2, o);
        s0 += __shfl_down_sync(0xffffffffu, s0, o);
        s1 += __shfl_down_sync(0xffffffffu, s1, o);
        s2 += __shfl_down_sync(0xffffffffu, s2, o);
    }

    if (lane == 0) {
        const float invBN = 1.0f / ((float)B_ * (float)N_);
        const float invBD = 1.0f / ((float)B_ * (float)D_);

        float bce_merged = -a0 * invBN;
        float bce_text   = -a1 * invBN;
        float bce_rec    = -a2 * invBN;
        float BCE = (bce_merged + bce_text + bce_rec) * (1.0f / 3.0f);

        float KLD1 = -0.5f * s0 * invBD;
        float KLD2 = s1 * invBD;            // ANNEAL = 1
        float wass = s2 * (1.0f / (float)B_);

        float lval = BCE + 0.5f * (KLD1 + KLD2) + wass;  // ANNEAL/2, EPSILON=1

        out[0] = lval;
        out[1] = BCE;
        out[2] = wass;
        out[3] = bce_rec;
        out[4] = bce_text;
        out[5] = bce_merged;
    }
}

extern "C" void kernel_launch(void* const* d_in, const int* in_sizes, int n_in,
                              void* d_out, int out_size) {
    const float* recon = (const float*)d_in[0];
    const float* x     = (const float*)d_in[1];
    const float* z     = (const float*)d_in[2];
    const float* mu    = (const float*)d_in[3];
    const float* lv    = (const float*)d_in[4];
    const float* text  = (const float*)d_in[5];
    const float* rec   = (const float*)d_in[6];
    const float* pmu   = (const float*)d_in[7];
    const float* plv   = (const float*)d_in[8];
    // d_in[9] = train_items, unused by the loss

    pass1_kernel<<<P1_GRID, P1_TPB>>>((const float4*)recon, (const float4*)x,
                                      (const float4*)text, (const float4*)rec,
                                      (const float4*)z, (const float4*)mu,
                                      (const float4*)lv, (const float4*)pmu,
                                      (const float4*)plv);

    // PDL launch: fixup is scheduled while pass1 drains; the device-side
    // cudaGridDependencySynchronize() enforces the data dependency.
    cudaLaunchConfig_t cfg = {};
    cfg.gridDim  = dim3(1, 1, 1);
    cfg.blockDim = dim3(1024, 1, 1);
    cfg.dynamicSmemBytes = 0;
    cfg.stream = 0;
    cudaLaunchAttribute attrs[1];
    attrs[0].id = cudaLaunchAttributeProgrammaticStreamSerialization;
    attrs[0].val.programmaticStreamSerializationAllowed = 1;
    cfg.attrs = attrs;
    cfg.numAttrs = 1;
    float* outp = (float*)d_out;
    cudaLaunchKernelEx(&cfg, fixup_kernel, outp);
}